// round 1
// baseline (speedup 1.0000x reference)
#include <cuda_runtime.h>
#include <math_constants.h>

// ---------------------------------------------------------------------------
// QKV_Attention: xsa (4,1024,512) f32, Wq (4096,512) f32
//   q    = xsa @ Wq^T                      -> scratch g_q (4096 x 4096)
//   h    = q_bk @ xsa_b^T / sqrt(512)      -> written into pijk output region
//   p    = softmax_rows(h)                 -> in place
//   y    = p @ xsa_b                       -> xid output region
// out = [ xid (4*1024*4096) | pijk (4*1024*8*1024) ]  (50,331,648 f32)
// ---------------------------------------------------------------------------

#define BM 128
#define BN 128
#define BK 16
#define TM 8
#define TN 8
#define NTHREADS 256
#define SMPAD 4

// 64 MB scratch for q (allocation-free rule: __device__ global array)
__device__ float g_q[4096UL * 4096UL];

// ---------------------------------------------------------------------------
// NT GEMM: C[m,n] = alpha * sum_k A[m,k] * B[n,k]
// A: M x K row-major (lda), B: N x K row-major (ldb), C: M x N (ldc)
// Batched over blockIdx.z = zb*Kcnt + zk with independent b/k strides.
// ---------------------------------------------------------------------------
__global__ __launch_bounds__(NTHREADS, 2)
void gemm_nt_kernel(const float* __restrict__ A, int lda, long sAb, long sAk,
                    const float* __restrict__ B, int ldb, long sBb, long sBk,
                    float* __restrict__ C, int ldc, long sCb, long sCk,
                    int M, int N, int Kdim, float alpha, int Kcnt)
{
    __shared__ float As[BK][BM + SMPAD];
    __shared__ float Bs[BK][BN + SMPAD];

    const int z  = blockIdx.z;
    const int zb = z / Kcnt;
    const int zk = z - zb * Kcnt;
    A += (size_t)zb * sAb + (size_t)zk * sAk;
    B += (size_t)zb * sBb + (size_t)zk * sBk;
    C += (size_t)zb * sCb + (size_t)zk * sCk;

    const int tid = threadIdx.x;
    const int rowBase = blockIdx.y * BM;
    const int colBase = blockIdx.x * BN;

    const int lr = tid >> 2;          // 0..63
    const int lc = (tid & 3) << 2;    // 0,4,8,12

    const int ty = tid >> 4;          // 0..15
    const int tx = tid & 15;          // 0..15

    float acc[TM][TN];
#pragma unroll
    for (int i = 0; i < TM; i++)
#pragma unroll
        for (int j = 0; j < TN; j++) acc[i][j] = 0.0f;

    for (int k0 = 0; k0 < Kdim; k0 += BK) {
        // load A tile (BM x BK), transposed into As[k][m]
        {
            const float4 a0 = *(const float4*)(A + (size_t)(rowBase + lr)      * lda + k0 + lc);
            const float4 a1 = *(const float4*)(A + (size_t)(rowBase + lr + 64) * lda + k0 + lc);
            As[lc + 0][lr] = a0.x; As[lc + 1][lr] = a0.y;
            As[lc + 2][lr] = a0.z; As[lc + 3][lr] = a0.w;
            As[lc + 0][lr + 64] = a1.x; As[lc + 1][lr + 64] = a1.y;
            As[lc + 2][lr + 64] = a1.z; As[lc + 3][lr + 64] = a1.w;
        }
        // load B tile (BN x BK), transposed into Bs[k][n]
        {
            const float4 b0 = *(const float4*)(B + (size_t)(colBase + lr)      * ldb + k0 + lc);
            const float4 b1 = *(const float4*)(B + (size_t)(colBase + lr + 64) * ldb + k0 + lc);
            Bs[lc + 0][lr] = b0.x; Bs[lc + 1][lr] = b0.y;
            Bs[lc + 2][lr] = b0.z; Bs[lc + 3][lr] = b0.w;
            Bs[lc + 0][lr + 64] = b1.x; Bs[lc + 1][lr + 64] = b1.y;
            Bs[lc + 2][lr + 64] = b1.z; Bs[lc + 3][lr + 64] = b1.w;
        }
        __syncthreads();

#pragma unroll
        for (int kk = 0; kk < BK; kk++) {
            float a[TM], b[TN];
#pragma unroll
            for (int i = 0; i < TM; i++) a[i] = As[kk][ty * TM + i];
#pragma unroll
            for (int j = 0; j < TN; j++) b[j] = Bs[kk][tx * TN + j];
#pragma unroll
            for (int i = 0; i < TM; i++)
#pragma unroll
                for (int j = 0; j < TN; j++)
                    acc[i][j] = fmaf(a[i], b[j], acc[i][j]);
        }
        __syncthreads();
    }

    // store
#pragma unroll
    for (int i = 0; i < TM; i++) {
        const size_t row = (size_t)(rowBase + ty * TM + i);
        float4* cp = (float4*)(C + row * ldc + colBase + tx * TN);
        float4 v0, v1;
        v0.x = alpha * acc[i][0]; v0.y = alpha * acc[i][1];
        v0.z = alpha * acc[i][2]; v0.w = alpha * acc[i][3];
        v1.x = alpha * acc[i][4]; v1.y = alpha * acc[i][5];
        v1.z = alpha * acc[i][6]; v1.w = alpha * acc[i][7];
        cp[0] = v0; cp[1] = v1;
    }
}

// ---------------------------------------------------------------------------
// NN GEMM: C[m,n] = alpha * sum_k A[m,k] * B[k,n]
// A: M x K row-major (lda), B: K x N row-major (ldb), C: M x N (ldc)
// ---------------------------------------------------------------------------
__global__ __launch_bounds__(NTHREADS, 2)
void gemm_nn_kernel(const float* __restrict__ A, int lda, long sAb, long sAk,
                    const float* __restrict__ B, int ldb, long sBb, long sBk,
                    float* __restrict__ C, int ldc, long sCb, long sCk,
                    int M, int N, int Kdim, float alpha, int Kcnt)
{
    __shared__ float As[BK][BM + SMPAD];
    __shared__ float Bs[BK][BN + SMPAD];

    const int z  = blockIdx.z;
    const int zb = z / Kcnt;
    const int zk = z - zb * Kcnt;
    A += (size_t)zb * sAb + (size_t)zk * sAk;
    B += (size_t)zb * sBb + (size_t)zk * sBk;
    C += (size_t)zb * sCb + (size_t)zk * sCk;

    const int tid = threadIdx.x;
    const int rowBase = blockIdx.y * BM;
    const int colBase = blockIdx.x * BN;

    const int lr = tid >> 2;          // 0..63 (A tile)
    const int lc = (tid & 3) << 2;

    const int br = tid >> 5;          // 0..7  (B tile)
    const int bc = (tid & 31) << 2;   // 0..124

    const int ty = tid >> 4;
    const int tx = tid & 15;

    float acc[TM][TN];
#pragma unroll
    for (int i = 0; i < TM; i++)
#pragma unroll
        for (int j = 0; j < TN; j++) acc[i][j] = 0.0f;

    for (int k0 = 0; k0 < Kdim; k0 += BK) {
        // A tile (BM x BK) transposed into As[k][m]
        {
            const float4 a0 = *(const float4*)(A + (size_t)(rowBase + lr)      * lda + k0 + lc);
            const float4 a1 = *(const float4*)(A + (size_t)(rowBase + lr + 64) * lda + k0 + lc);
            As[lc + 0][lr] = a0.x; As[lc + 1][lr] = a0.y;
            As[lc + 2][lr] = a0.z; As[lc + 3][lr] = a0.w;
            As[lc + 0][lr + 64] = a1.x; As[lc + 1][lr + 64] = a1.y;
            As[lc + 2][lr + 64] = a1.z; As[lc + 3][lr + 64] = a1.w;
        }
        // B tile (BK x BN) loaded directly into Bs[k][n]
        {
            *(float4*)&Bs[br][bc]     = *(const float4*)(B + (size_t)(k0 + br)     * ldb + colBase + bc);
            *(float4*)&Bs[br + 8][bc] = *(const float4*)(B + (size_t)(k0 + br + 8) * ldb + colBase + bc);
        }
        __syncthreads();

#pragma unroll
        for (int kk = 0; kk < BK; kk++) {
            float a[TM], b[TN];
#pragma unroll
            for (int i = 0; i < TM; i++) a[i] = As[kk][ty * TM + i];
#pragma unroll
            for (int j = 0; j < TN; j++) b[j] = Bs[kk][tx * TN + j];
#pragma unroll
            for (int i = 0; i < TM; i++)
#pragma unroll
                for (int j = 0; j < TN; j++)
                    acc[i][j] = fmaf(a[i], b[j], acc[i][j]);
        }
        __syncthreads();
    }

#pragma unroll
    for (int i = 0; i < TM; i++) {
        const size_t row = (size_t)(rowBase + ty * TM + i);
        float4* cp = (float4*)(C + row * ldc + colBase + tx * TN);
        float4 v0, v1;
        v0.x = alpha * acc[i][0]; v0.y = alpha * acc[i][1];
        v0.z = alpha * acc[i][2]; v0.w = alpha * acc[i][3];
        v1.x = alpha * acc[i][4]; v1.y = alpha * acc[i][5];
        v1.z = alpha * acc[i][6]; v1.w = alpha * acc[i][7];
        cp[0] = v0; cp[1] = v1;
    }
}

// ---------------------------------------------------------------------------
// In-place row softmax over rows of 1024 floats. One block (256 thr) per row.
// ---------------------------------------------------------------------------
__global__ void softmax_rows_kernel(float* __restrict__ p)
{
    __shared__ float red[32];
    float* row = p + (size_t)blockIdx.x * 1024;
    const int t = threadIdx.x;

    float4 v = ((const float4*)row)[t];

    // row max
    float m = fmaxf(fmaxf(v.x, v.y), fmaxf(v.z, v.w));
#pragma unroll
    for (int o = 16; o; o >>= 1) m = fmaxf(m, __shfl_xor_sync(0xffffffffu, m, o));
    if ((t & 31) == 0) red[t >> 5] = m;
    __syncthreads();
    if (t < 32) {
        float mm = (t < 8) ? red[t] : -CUDART_INF_F;
#pragma unroll
        for (int o = 4; o; o >>= 1) mm = fmaxf(mm, __shfl_xor_sync(0xffffffffu, mm, o));
        if (t == 0) red[0] = mm;
    }
    __syncthreads();
    m = red[0];
    __syncthreads();

    v.x = __expf(v.x - m); v.y = __expf(v.y - m);
    v.z = __expf(v.z - m); v.w = __expf(v.w - m);

    // row sum
    float s = v.x + v.y + v.z + v.w;
#pragma unroll
    for (int o = 16; o; o >>= 1) s += __shfl_xor_sync(0xffffffffu, s, o);
    if ((t & 31) == 0) red[t >> 5] = s;
    __syncthreads();
    if (t < 32) {
        float ss = (t < 8) ? red[t] : 0.0f;
#pragma unroll
        for (int o = 4; o; o >>= 1) ss += __shfl_xor_sync(0xffffffffu, ss, o);
        if (t == 0) red[0] = ss;
    }
    __syncthreads();
    const float inv = 1.0f / red[0];

    v.x *= inv; v.y *= inv; v.z *= inv; v.w *= inv;
    ((float4*)row)[t] = v;
}

// ---------------------------------------------------------------------------
extern "C" void kernel_launch(void* const* d_in, const int* in_sizes, int n_in,
                              void* d_out, int out_size)
{
    (void)in_sizes; (void)n_in; (void)out_size;
    const float* xsa = (const float*)d_in[0];   // (4,1024,512)
    const float* Wq  = (const float*)d_in[1];   // (4096,512)
    float* out  = (float*)d_out;
    float* xid  = out;                           // 4*1024*4096 = 16777216
    float* pijk = out + 16777216UL;              // 4*1024*8*1024 = 33554432

    float* qbuf = nullptr;
    cudaGetSymbolAddress((void**)&qbuf, g_q);

    const dim3 blk(NTHREADS);
    const float inv_sqrt_e = 0.044194173824159216f;  // 1/sqrt(512)

    // K1: q = xsa @ Wq^T   (M=4096, N=4096, K=512)
    gemm_nt_kernel<<<dim3(32, 32, 1), blk>>>(
        xsa, 512, 0, 0,
        Wq,  512, 0, 0,
        qbuf, 4096, 0, 0,
        4096, 4096, 512, 1.0f, 1);

    // K2: logits[b,k] = q_bk @ xsa_b^T / sqrt(E)   (M=1024, N=1024, K=512), 32 batches
    gemm_nt_kernel<<<dim3(8, 8, 32), blk>>>(
        qbuf, 4096, 4194304L, 512L,
        xsa,  512,  524288L,  0L,
        pijk, 8192, 8388608L, 1024L,
        1024, 1024, 512, inv_sqrt_e, 8);

    // K3: softmax over rows (32768 rows of 1024), in place
    softmax_rows_kernel<<<32768, 256>>>(pijk);

    // K4: y[b,k] = p_bk @ xsa_b   (M=1024, N=512, K=1024), 32 batches
    gemm_nn_kernel<<<dim3(4, 8, 32), blk>>>(
        pijk, 8192, 8388608L, 1024L,
        xsa,  512,  524288L,  0L,
        xid,  4096, 4194304L, 512L,
        1024, 512, 1024, 1.0f, 8);
}

// round 4
// speedup vs baseline: 3.1116x; 3.1116x over previous
#include <cuda_runtime.h>
#include <cstdint>
#include <math_constants.h>

// ============================================================================
// QKV_Attention via mma.sync tf32 (legacy tensor path; tcgen05 is 'a'-gated
// and this build's PTX target is plain sm_103).
//   prep : xsa->g_xr (tf32-rounded), Wq->g_wr (rounded), xsa->g_xt (T, rounded)
//   K1   : q = g_xr @ g_wr^T      -> g_q (rounded in epilogue)
//   K2   : h = q_bk @ g_xr_b^T /sqrt(E) -> pijk (exact)
//   K3   : softmax rows in place; also writes rounded copy -> g_pr
//   K4   : y = g_pr_bk @ g_xt_b^T -> xid   (pr rows stride 8192!)
// ============================================================================

#define BM 128
#define BN 128
#define BK 32
#define NTHREADS 256
#define ASTRIDE 36                      // padded floats per smem row
#define ROWB (ASTRIDE*4)                // 144 bytes
#define TILEB (128*ROWB)                // 18432 bytes per tile
#define STAGEB (2*TILEB)                // A+B
#define DSMEMB (2*STAGEB)               // double buffer = 73728

__device__ float g_q [4096UL*4096UL];        // 64 MB
__device__ float g_xt[4UL*512UL*1024UL];     //  8 MB
__device__ float g_xr[4UL*1024UL*512UL];     //  8 MB
__device__ float g_wr[4096UL*512UL];         //  8 MB
__device__ float g_pr[32768UL*1024UL];       // 128 MB

// ---------------------------------------------------------------- helpers
__device__ __forceinline__ uint32_t smem_u32(const void* p) {
    uint32_t a;
    asm("{ .reg .u64 t; cvta.to.shared.u64 t, %1; cvt.u32.u64 %0, t; }"
        : "=r"(a) : "l"(p));
    return a;
}
__device__ __forceinline__ float tf32_rna(float x) {
    uint32_t u;
    asm("cvt.rna.tf32.f32 %0, %1;" : "=r"(u) : "f"(x));
    return __uint_as_float(u);
}
#define CP16(d, s) \
    asm volatile("cp.async.cg.shared.global [%0], [%1], 16;" :: "r"(d), "l"(s))
#define CP_COMMIT() asm volatile("cp.async.commit_group;" ::: "memory")
#define CP_WAIT1()  asm volatile("cp.async.wait_group 1;" ::: "memory")
#define CP_WAIT0()  asm volatile("cp.async.wait_group 0;" ::: "memory")

__device__ __forceinline__ void mma_tf32(float c[4], const uint32_t a[4], const uint32_t b[2]) {
    asm volatile(
        "mma.sync.aligned.m16n8k8.row.col.f32.tf32.tf32.f32 "
        "{%0,%1,%2,%3}, {%4,%5,%6,%7}, {%8,%9}, {%0,%1,%2,%3};"
        : "+f"(c[0]), "+f"(c[1]), "+f"(c[2]), "+f"(c[3])
        : "r"(a[0]), "r"(a[1]), "r"(a[2]), "r"(a[3]), "r"(b[0]), "r"(b[1]));
}

// ============================================================================
// NT GEMM: C[m,n] = alpha * sum_k A[m,k]*B[n,k].  M,N multiples of 128,
// K multiple of 32. Batched via blockIdx.z (zb*Kcnt+zk strides).
// roundOut: store tf32-rounded values (for tensors that feed later GEMMs).
// ============================================================================
__global__ void __launch_bounds__(NTHREADS, 2)
gemm_mma(const float* __restrict__ A, int lda, long sAb, long sAk,
         const float* __restrict__ B, int ldb, long sBb, long sBk,
         float* __restrict__ C, int ldc, long sCb, long sCk,
         int Kdim, float alpha, int Kcnt, int roundOut)
{
    extern __shared__ float sm[];
    const uint32_t smb = smem_u32(sm);

    const int tid  = threadIdx.x;
    const int wid  = tid >> 5;
    const int lane = tid & 31;
    const int gid  = lane >> 2;      // 0..7
    const int tg   = lane & 3;       // 0..3
    const int warpMoff = (wid >> 2) * 64;   // 0,64
    const int warpNoff = (wid & 3) * 32;    // 0..96

    const int z  = blockIdx.z;
    const int zb = z / Kcnt;
    const int zk = z - zb * Kcnt;
    const float* Ab = A + (size_t)zb * sAb + (size_t)zk * sAk + (size_t)(blockIdx.y * BM) * lda;
    const float* Bb = B + (size_t)zb * sBb + (size_t)zk * sBk + (size_t)(blockIdx.x * BN) * ldb;
    float* Cb = C + (size_t)zb * sCb + (size_t)zk * sCk
                  + (size_t)(blockIdx.y * BM) * ldc + (size_t)(blockIdx.x * BN);

    const int numK = Kdim >> 5;

    // per-thread cp.async coords: 4 chunks per tile
    int rowA[4], chA[4];
#pragma unroll
    for (int i = 0; i < 4; i++) {
        int idx = tid + i * NTHREADS;     // 0..1023
        rowA[i] = idx >> 3;
        chA[i]  = idx & 7;
    }

    float c[4][4][4];
#pragma unroll
    for (int i = 0; i < 4; i++)
#pragma unroll
        for (int j = 0; j < 4; j++)
#pragma unroll
            for (int r = 0; r < 4; r++) c[i][j][r] = 0.0f;

    // ---- prologue: stage 0
    {
        const float* Asrc = Ab;
        const float* Bsrc = Bb;
#pragma unroll
        for (int i = 0; i < 4; i++) {
            uint32_t dA = smb + rowA[i] * ROWB + chA[i] * 16;
            CP16(dA, Asrc + (size_t)rowA[i] * lda + chA[i] * 4);
            uint32_t dB = smb + TILEB + rowA[i] * ROWB + chA[i] * 16;
            CP16(dB, Bsrc + (size_t)rowA[i] * ldb + chA[i] * 4);
        }
        CP_COMMIT();
    }

    for (int kt = 0; kt < numK; kt++) {
        if (kt + 1 < numK) {
            const int nb = (kt + 1) & 1;
            const float* Asrc = Ab + (kt + 1) * BK;
            const float* Bsrc = Bb + (kt + 1) * BK;
#pragma unroll
            for (int i = 0; i < 4; i++) {
                uint32_t dA = smb + nb * STAGEB + rowA[i] * ROWB + chA[i] * 16;
                CP16(dA, Asrc + (size_t)rowA[i] * lda + chA[i] * 4);
                uint32_t dB = smb + nb * STAGEB + TILEB + rowA[i] * ROWB + chA[i] * 16;
                CP16(dB, Bsrc + (size_t)rowA[i] * ldb + chA[i] * 4);
            }
            CP_COMMIT();
            CP_WAIT1();
        } else {
            CP_WAIT0();
        }
        __syncthreads();

        const float* As = sm + (kt & 1) * (STAGEB / 4);
        const float* Bs = As + (TILEB / 4);

#pragma unroll
        for (int kk = 0; kk < 4; kk++) {
            const int k0 = kk * 8;
            uint32_t a[4][4], b[4][2];
#pragma unroll
            for (int i = 0; i < 4; i++) {
                const float* ap = As + (warpMoff + i * 16 + gid) * ASTRIDE + k0 + tg;
                a[i][0] = __float_as_uint(ap[0]);
                a[i][1] = __float_as_uint(ap[8 * ASTRIDE]);
                a[i][2] = __float_as_uint(ap[4]);
                a[i][3] = __float_as_uint(ap[8 * ASTRIDE + 4]);
            }
#pragma unroll
            for (int j = 0; j < 4; j++) {
                const float* bp = Bs + (warpNoff + j * 8 + gid) * ASTRIDE + k0 + tg;
                b[j][0] = __float_as_uint(bp[0]);
                b[j][1] = __float_as_uint(bp[4]);
            }
#pragma unroll
            for (int i = 0; i < 4; i++)
#pragma unroll
                for (int j = 0; j < 4; j++)
                    mma_tf32(c[i][j], a[i], b[j]);
        }
        __syncthreads();
    }

    // ---- epilogue
#pragma unroll
    for (int i = 0; i < 4; i++) {
        const int r0 = warpMoff + i * 16 + gid;
#pragma unroll
        for (int j = 0; j < 4; j++) {
            const int cc = warpNoff + j * 8 + tg * 2;
            float2 v0, v1;
            v0.x = alpha * c[i][j][0]; v0.y = alpha * c[i][j][1];
            v1.x = alpha * c[i][j][2]; v1.y = alpha * c[i][j][3];
            if (roundOut) {
                v0.x = tf32_rna(v0.x); v0.y = tf32_rna(v0.y);
                v1.x = tf32_rna(v1.x); v1.y = tf32_rna(v1.y);
            }
            *(float2*)(Cb + (size_t)r0 * ldc + cc)       = v0;
            *(float2*)(Cb + (size_t)(r0 + 8) * ldc + cc) = v1;
        }
    }
}

// ============================================================================
// prep: round xsa and Wq to tf32 grid
// ============================================================================
__global__ void round_kernel(const float* __restrict__ in, float* __restrict__ out, int n4)
{
    int i = blockIdx.x * blockDim.x + threadIdx.x;
    if (i >= n4) return;
    float4 v = ((const float4*)in)[i];
    v.x = tf32_rna(v.x); v.y = tf32_rna(v.y);
    v.z = tf32_rna(v.z); v.w = tf32_rna(v.w);
    ((float4*)out)[i] = v;
}

// transpose xsa (b,1024,512) -> g_xt (b,512,1024), tf32-rounded
__global__ void transpose_kernel(const float* __restrict__ in, float* __restrict__ out)
{
    __shared__ float t[32][33];
    const int b = blockIdx.z;
    const int l0 = blockIdx.x * 32, e0 = blockIdx.y * 32;
    in  += (size_t)b * 524288;
    out += (size_t)b * 524288;
    const int x = threadIdx.x, y = threadIdx.y;  // 32 x 8
#pragma unroll
    for (int i = 0; i < 32; i += 8)
        t[y + i][x] = tf32_rna(in[(size_t)(l0 + y + i) * 512 + e0 + x]);
    __syncthreads();
#pragma unroll
    for (int i = 0; i < 32; i += 8)
        out[(size_t)(e0 + y + i) * 1024 + l0 + x] = t[x][y + i];
}

// ============================================================================
// softmax rows of 1024, in place; also writes tf32-rounded copy to pr
// ============================================================================
__global__ void softmax_rows_kernel(float* __restrict__ p, float* __restrict__ pr)
{
    __shared__ float red[32];
    const size_t roff = (size_t)blockIdx.x * 1024;
    float* row = p + roff;
    const int t = threadIdx.x;

    float4 v = ((const float4*)row)[t];

    float m = fmaxf(fmaxf(v.x, v.y), fmaxf(v.z, v.w));
#pragma unroll
    for (int o = 16; o; o >>= 1) m = fmaxf(m, __shfl_xor_sync(0xffffffffu, m, o));
    if ((t & 31) == 0) red[t >> 5] = m;
    __syncthreads();
    if (t < 32) {
        float mm = (t < 8) ? red[t] : -CUDART_INF_F;
#pragma unroll
        for (int o = 4; o; o >>= 1) mm = fmaxf(mm, __shfl_xor_sync(0xffffffffu, mm, o));
        if (t == 0) red[0] = mm;
    }
    __syncthreads();
    m = red[0];
    __syncthreads();

    v.x = __expf(v.x - m); v.y = __expf(v.y - m);
    v.z = __expf(v.z - m); v.w = __expf(v.w - m);

    float s = v.x + v.y + v.z + v.w;
#pragma unroll
    for (int o = 16; o; o >>= 1) s += __shfl_xor_sync(0xffffffffu, s, o);
    if ((t & 31) == 0) red[t >> 5] = s;
    __syncthreads();
    if (t < 32) {
        float ss = (t < 8) ? red[t] : 0.0f;
#pragma unroll
        for (int o = 4; o; o >>= 1) ss += __shfl_xor_sync(0xffffffffu, ss, o);
        if (t == 0) red[0] = ss;
    }
    __syncthreads();
    const float inv = 1.0f / red[0];

    v.x *= inv; v.y *= inv; v.z *= inv; v.w *= inv;
    ((float4*)row)[t] = v;

    float4 w;
    w.x = tf32_rna(v.x); w.y = tf32_rna(v.y);
    w.z = tf32_rna(v.z); w.w = tf32_rna(v.w);
    ((float4*)(pr + roff))[t] = w;
}

// ============================================================================
extern "C" void kernel_launch(void* const* d_in, const int* in_sizes, int n_in,
                              void* d_out, int out_size)
{
    (void)in_sizes; (void)n_in; (void)out_size;
    const float* xsa = (const float*)d_in[0];   // (4,1024,512)
    const float* Wq  = (const float*)d_in[1];   // (4096,512)
    float* out  = (float*)d_out;
    float* xid  = out;                          // 16777216 floats
    float* pijk = out + 16777216UL;             // 33554432 floats

    float *qbuf, *xt, *xr, *wr, *pr;
    cudaGetSymbolAddress((void**)&qbuf, g_q);
    cudaGetSymbolAddress((void**)&xt,   g_xt);
    cudaGetSymbolAddress((void**)&xr,   g_xr);
    cudaGetSymbolAddress((void**)&wr,   g_wr);
    cudaGetSymbolAddress((void**)&pr,   g_pr);

    cudaFuncSetAttribute(gemm_mma, cudaFuncAttributeMaxDynamicSharedMemorySize, DSMEMB);

    const float inv_sqrt_e = 0.044194173824159216f;  // 1/sqrt(512)

    // prep: rounded operands
    round_kernel<<<2048, 256>>>(xsa, xr, 524288);   // 2M floats
    round_kernel<<<2048, 256>>>(Wq,  wr, 524288);
    transpose_kernel<<<dim3(32, 16, 4), dim3(32, 8)>>>(xsa, xt);

    // K1: q = xr @ wr^T    M=4096 N=4096 K=512  (round output: feeds K2)
    gemm_mma<<<dim3(32, 32, 1), NTHREADS, DSMEMB>>>(
        xr, 512, 0, 0,
        wr, 512, 0, 0,
        qbuf, 4096, 0, 0,
        512, 1.0f, 1, 1);

    // K2: logits = q_bk @ xr_b^T / sqrt(E)   M=1024 N=1024 K=512, 32 batches
    gemm_mma<<<dim3(8, 8, 32), NTHREADS, DSMEMB>>>(
        qbuf, 4096, 4194304L, 512L,
        xr,   512,  524288L,  0L,
        pijk, 8192, 8388608L, 1024L,
        512, inv_sqrt_e, 8, 0);

    // K3: softmax rows -> pijk exact, pr rounded
    softmax_rows_kernel<<<32768, 256>>>(pijk, pr);

    // K4: y = pr_bk @ xt_b^T   M=1024 N=512 K=1024, 32 batches
    // pr has pijk's (b,l,k,m) layout: row stride (over l) = 8192, k stride = 1024
    gemm_mma<<<dim3(4, 8, 32), NTHREADS, DSMEMB>>>(
        pr, 8192, 8388608L, 1024L,
        xt, 1024, 524288L,  0L,
        xid, 4096, 4194304L, 512L,
        1024, 1.0f, 8, 0);
}

// round 5
// speedup vs baseline: 6.4473x; 2.0720x over previous
#include <cuda_runtime.h>
#include <cuda_fp16.h>
#include <cstdint>
#include <math_constants.h>

// ============================================================================
// QKV_Attention via mma.sync m16n8k16 fp16 (f32 accumulate) + ldmatrix.
//   prep : xh = fp16(xsa), wh = fp16(Wq), xth = fp16(xsa^T per batch)
//   K1   : q = xh @ wh^T              -> g_qh (fp16)
//   K2   : h = qh_bk @ xh_b^T /sqrt(E) -> pijk (f32)
//   K3   : softmax rows in place (f32) + fp16 copy -> g_ph
//   K4   : y = ph_bk @ xth_b^T        -> xid (f32)
// fp16 RN operand rounding (2^-11) == tf32 RNA; accum stays f32.
// ============================================================================

#define NTHREADS 256
#define BK 64
#define TILEB 16384                 // 128 rows x 128 bytes (64 fp16)
#define STAGEB (2*TILEB)            // A + B
#define DSMEMB (2*STAGEB)           // double buffer = 65536

__device__ __half g_qh [4096UL*4096UL];      // 32 MB
__device__ __half g_xh [4UL*1024UL*512UL];   //  4 MB
__device__ __half g_wh [4096UL*512UL];       //  4 MB
__device__ __half g_xth[4UL*512UL*1024UL];   //  4 MB
__device__ __half g_ph [32768UL*1024UL];     // 64 MB

// ---------------------------------------------------------------- helpers
__device__ __forceinline__ uint32_t smem_u32(const void* p) {
    uint32_t a;
    asm("{ .reg .u64 t; cvta.to.shared.u64 t, %1; cvt.u32.u64 %0, t; }"
        : "=r"(a) : "l"(p));
    return a;
}
#define CP16(d, s) \
    asm volatile("cp.async.cg.shared.global [%0], [%1], 16;" :: "r"(d), "l"(s))
#define CP_COMMIT() asm volatile("cp.async.commit_group;" ::: "memory")
#define CP_WAIT1()  asm volatile("cp.async.wait_group 1;" ::: "memory")
#define CP_WAIT0()  asm volatile("cp.async.wait_group 0;" ::: "memory")

#define LDSM4(r, a) \
    asm volatile("ldmatrix.sync.aligned.m8n8.x4.shared.b16 {%0,%1,%2,%3}, [%4];" \
        : "=r"((r)[0]), "=r"((r)[1]), "=r"((r)[2]), "=r"((r)[3]) : "r"(a))

__device__ __forceinline__ void mma_f16(float c[4], const uint32_t a[4],
                                        uint32_t b0, uint32_t b1) {
    asm volatile(
        "mma.sync.aligned.m16n8k16.row.col.f32.f16.f16.f32 "
        "{%0,%1,%2,%3}, {%4,%5,%6,%7}, {%8,%9}, {%0,%1,%2,%3};"
        : "+f"(c[0]), "+f"(c[1]), "+f"(c[2]), "+f"(c[3])
        : "r"(a[0]), "r"(a[1]), "r"(a[2]), "r"(a[3]), "r"(b0), "r"(b1));
}

// load 128 rows x 64 fp16 (row stride ld elems) into XOR-swizzled smem tile
__device__ __forceinline__ void load_tile_h(uint32_t dst, const __half* g, int ld, int tid) {
#pragma unroll
    for (int i = 0; i < 4; i++) {
        int idx = tid + i * NTHREADS;     // 0..1023
        int row = idx >> 3;
        int c   = idx & 7;                // 16B chunk
        uint32_t off = (uint32_t)(row << 7) | (uint32_t)(((c ^ (row & 7)) << 4));
        CP16(dst + off, g + (size_t)row * ld + (c << 3));
    }
}

// ============================================================================
// NT GEMM (fp16 in, f32 acc): C[m,n] = alpha * sum_k A[m,k]*B[n,k]
// CTA tile 128x128, BK=64, 8 warps (2x4), warp tile 64x32.
// halfOut: C is __half*, else float*.
// ============================================================================
__global__ void __launch_bounds__(NTHREADS, 2)
gemm_h(const __half* __restrict__ A, int lda, long sAb, long sAk,
       const __half* __restrict__ B, int ldb, long sBb, long sBk,
       void* __restrict__ Cv, int ldc, long sCb, long sCk,
       int Kdim, float alpha, int Kcnt, int halfOut)
{
    extern __shared__ __half smh[];
    const uint32_t smb = smem_u32(smh);

    const int tid  = threadIdx.x;
    const int wid  = tid >> 5;
    const int lane = tid & 31;
    const int gid  = lane >> 2;
    const int tg   = lane & 3;
    const int warpMoff = (wid >> 2) * 64;   // 0,64
    const int warpNoff = (wid & 3) * 32;    // 0..96

    const int z  = blockIdx.z;
    const int zb = z / Kcnt;
    const int zk = z - zb * Kcnt;
    const __half* Ab = A + (size_t)zb * sAb + (size_t)zk * sAk + (size_t)(blockIdx.y * 128) * lda;
    const __half* Bb = B + (size_t)zb * sBb + (size_t)zk * sBk + (size_t)(blockIdx.x * 128) * ldb;
    const size_t cOff = (size_t)zb * sCb + (size_t)zk * sCk
                      + (size_t)(blockIdx.y * 128) * ldc + (size_t)(blockIdx.x * 128);

    const int numK = Kdim >> 6;

    float c[4][4][4];
#pragma unroll
    for (int i = 0; i < 4; i++)
#pragma unroll
        for (int j = 0; j < 4; j++)
#pragma unroll
            for (int r = 0; r < 4; r++) c[i][j][r] = 0.0f;

    // fixed per-lane ldmatrix row components
    const int rlA = lane & 15;                    // + lane>>4 selects k-chunk
    const int hiA = lane >> 4;
    const int rlB = ((lane >> 4) << 3) + (lane & 7);
    const int hiB = (lane >> 3) & 1;

    // ---- prologue
    load_tile_h(smb,          Ab, lda, tid);
    load_tile_h(smb + TILEB,  Bb, ldb, tid);
    CP_COMMIT();

    for (int kt = 0; kt < numK; kt++) {
        if (kt + 1 < numK) {
            const uint32_t nbb = smb + ((kt + 1) & 1) * STAGEB;
            load_tile_h(nbb,         Ab + (kt + 1) * BK, lda, tid);
            load_tile_h(nbb + TILEB, Bb + (kt + 1) * BK, ldb, tid);
            CP_COMMIT();
            CP_WAIT1();
        } else {
            CP_WAIT0();
        }
        __syncthreads();

        const uint32_t At = smb + (kt & 1) * STAGEB;
        const uint32_t Bt = At + TILEB;

#pragma unroll
        for (int kk = 0; kk < 4; kk++) {
            uint32_t a[4][4], bb[2][4];
            const int cA = kk * 2 + hiA;
            const int cB = kk * 2 + hiB;
#pragma unroll
            for (int i = 0; i < 4; i++) {
                const int row = warpMoff + i * 16 + rlA;
                uint32_t ad = At + ((uint32_t)row << 7)
                            + (uint32_t)(((cA ^ (row & 7)) << 4));
                LDSM4(a[i], ad);
            }
#pragma unroll
            for (int j = 0; j < 2; j++) {
                const int row = warpNoff + j * 16 + rlB;
                uint32_t bd = Bt + ((uint32_t)row << 7)
                            + (uint32_t)(((cB ^ (row & 7)) << 4));
                LDSM4(bb[j], bd);
            }
#pragma unroll
            for (int i = 0; i < 4; i++)
#pragma unroll
                for (int jj = 0; jj < 4; jj++)
                    mma_f16(c[i][jj], a[i], bb[jj >> 1][(jj & 1) * 2],
                                             bb[jj >> 1][(jj & 1) * 2 + 1]);
        }
        __syncthreads();
    }

    // ---- epilogue
    if (halfOut) {
        __half* Cb = (__half*)Cv + cOff;
#pragma unroll
        for (int i = 0; i < 4; i++) {
            const int r0 = warpMoff + i * 16 + gid;
#pragma unroll
            for (int jj = 0; jj < 4; jj++) {
                const int cc = warpNoff + jj * 8 + tg * 2;
                *(__half2*)(Cb + (size_t)r0 * ldc + cc) =
                    __floats2half2_rn(alpha * c[i][jj][0], alpha * c[i][jj][1]);
                *(__half2*)(Cb + (size_t)(r0 + 8) * ldc + cc) =
                    __floats2half2_rn(alpha * c[i][jj][2], alpha * c[i][jj][3]);
            }
        }
    } else {
        float* Cb = (float*)Cv + cOff;
#pragma unroll
        for (int i = 0; i < 4; i++) {
            const int r0 = warpMoff + i * 16 + gid;
#pragma unroll
            for (int jj = 0; jj < 4; jj++) {
                const int cc = warpNoff + jj * 8 + tg * 2;
                float2 v0, v1;
                v0.x = alpha * c[i][jj][0]; v0.y = alpha * c[i][jj][1];
                v1.x = alpha * c[i][jj][2]; v1.y = alpha * c[i][jj][3];
                *(float2*)(Cb + (size_t)r0 * ldc + cc)       = v0;
                *(float2*)(Cb + (size_t)(r0 + 8) * ldc + cc) = v1;
            }
        }
    }
}

// ============================================================================
// prep: f32 -> fp16
// ============================================================================
__global__ void cvt_h(const float* __restrict__ in, __half* __restrict__ out, int n4)
{
    int i = blockIdx.x * blockDim.x + threadIdx.x;
    if (i >= n4) return;
    float4 v = ((const float4*)in)[i];
    ((__half2*)out)[2 * i]     = __floats2half2_rn(v.x, v.y);
    ((__half2*)out)[2 * i + 1] = __floats2half2_rn(v.z, v.w);
}

// transpose xsa (b,1024,512) f32 -> g_xth (b,512,1024) fp16
__global__ void transpose_h(const float* __restrict__ in, __half* __restrict__ out)
{
    __shared__ float t[32][33];
    const int b = blockIdx.z;
    const int l0 = blockIdx.x * 32, e0 = blockIdx.y * 32;
    in  += (size_t)b * 524288;
    out += (size_t)b * 524288;
    const int x = threadIdx.x, y = threadIdx.y;  // 32 x 8
#pragma unroll
    for (int i = 0; i < 32; i += 8)
        t[y + i][x] = in[(size_t)(l0 + y + i) * 512 + e0 + x];
    __syncthreads();
#pragma unroll
    for (int i = 0; i < 32; i += 8)
        out[(size_t)(e0 + y + i) * 1024 + l0 + x] = __float2half_rn(t[x][y + i]);
}

// ============================================================================
// softmax rows of 1024, in place (f32); also writes fp16 copy to ph
// ============================================================================
__global__ void softmax_rows_kernel(float* __restrict__ p, __half* __restrict__ ph)
{
    __shared__ float red[32];
    const size_t roff = (size_t)blockIdx.x * 1024;
    float* row = p + roff;
    const int t = threadIdx.x;

    float4 v = ((const float4*)row)[t];

    float m = fmaxf(fmaxf(v.x, v.y), fmaxf(v.z, v.w));
#pragma unroll
    for (int o = 16; o; o >>= 1) m = fmaxf(m, __shfl_xor_sync(0xffffffffu, m, o));
    if ((t & 31) == 0) red[t >> 5] = m;
    __syncthreads();
    if (t < 32) {
        float mm = (t < 8) ? red[t] : -CUDART_INF_F;
#pragma unroll
        for (int o = 4; o; o >>= 1) mm = fmaxf(mm, __shfl_xor_sync(0xffffffffu, mm, o));
        if (t == 0) red[0] = mm;
    }
    __syncthreads();
    m = red[0];
    __syncthreads();

    v.x = __expf(v.x - m); v.y = __expf(v.y - m);
    v.z = __expf(v.z - m); v.w = __expf(v.w - m);

    float s = v.x + v.y + v.z + v.w;
#pragma unroll
    for (int o = 16; o; o >>= 1) s += __shfl_xor_sync(0xffffffffu, s, o);
    if ((t & 31) == 0) red[t >> 5] = s;
    __syncthreads();
    if (t < 32) {
        float ss = (t < 8) ? red[t] : 0.0f;
#pragma unroll
        for (int o = 4; o; o >>= 1) ss += __shfl_xor_sync(0xffffffffu, ss, o);
        if (t == 0) red[0] = ss;
    }
    __syncthreads();
    const float inv = 1.0f / red[0];

    v.x *= inv; v.y *= inv; v.z *= inv; v.w *= inv;
    ((float4*)row)[t] = v;

    __half2* pp = (__half2*)(ph + roff);
    pp[2 * t]     = __floats2half2_rn(v.x, v.y);
    pp[2 * t + 1] = __floats2half2_rn(v.z, v.w);
}

// ============================================================================
extern "C" void kernel_launch(void* const* d_in, const int* in_sizes, int n_in,
                              void* d_out, int out_size)
{
    (void)in_sizes; (void)n_in; (void)out_size;
    const float* xsa = (const float*)d_in[0];   // (4,1024,512)
    const float* Wq  = (const float*)d_in[1];   // (4096,512)
    float* out  = (float*)d_out;
    float* xid  = out;                          // 16777216 floats
    float* pijk = out + 16777216UL;             // 33554432 floats

    __half *qh, *xh, *wh, *xth, *ph;
    cudaGetSymbolAddress((void**)&qh,  g_qh);
    cudaGetSymbolAddress((void**)&xh,  g_xh);
    cudaGetSymbolAddress((void**)&wh,  g_wh);
    cudaGetSymbolAddress((void**)&xth, g_xth);
    cudaGetSymbolAddress((void**)&ph,  g_ph);

    cudaFuncSetAttribute(gemm_h, cudaFuncAttributeMaxDynamicSharedMemorySize, DSMEMB);

    const float inv_sqrt_e = 0.044194173824159216f;  // 1/sqrt(512)

    // prep
    cvt_h<<<2048, 256>>>(xsa, xh, 524288);
    cvt_h<<<2048, 256>>>(Wq,  wh, 524288);
    transpose_h<<<dim3(32, 16, 4), dim3(32, 8)>>>(xsa, xth);

    // K1: q = xh @ wh^T   M=4096 N=4096 K=512, fp16 out
    gemm_h<<<dim3(32, 32, 1), NTHREADS, DSMEMB>>>(
        xh, 512, 0, 0,
        wh, 512, 0, 0,
        qh, 4096, 0, 0,
        512, 1.0f, 1, 1);

    // K2: logits = qh_bk @ xh_b^T / sqrt(E)   M=1024 N=1024 K=512, 32 batches
    gemm_h<<<dim3(8, 8, 32), NTHREADS, DSMEMB>>>(
        qh, 4096, 4194304L, 512L,
        xh, 512,  524288L,  0L,
        pijk, 8192, 8388608L, 1024L,
        512, inv_sqrt_e, 8, 0);

    // K3: softmax -> pijk f32 (output) + ph fp16 (K4 operand)
    softmax_rows_kernel<<<32768, 256>>>(pijk, ph);

    // K4: y = ph_bk @ xth_b^T   M=1024 N=512 K=1024, 32 batches
    // ph layout (b,l,k,m): row stride 8192, k stride 1024
    gemm_h<<<dim3(4, 8, 32), NTHREADS, DSMEMB>>>(
        ph,  8192, 8388608L, 1024L,
        xth, 1024, 524288L,  0L,
        xid, 4096, 4194304L, 512L,
        1024, 1.0f, 8, 0);
}

// round 6
// speedup vs baseline: 6.4675x; 1.0031x over previous
#include <cuda_runtime.h>
#include <cuda_fp16.h>
#include <cstdint>
#include <math_constants.h>

// ============================================================================
// QKV_Attention via mma.sync m16n8k16 fp16 (f32 accumulate) + ldmatrix.
// Round 6: 3-stage cp.async pipeline, ONE __syncthreads per k-tile.
//   prep : xh = fp16(xsa), wh = fp16(Wq), xth = fp16(xsa^T per batch)
//   K1   : q = xh @ wh^T              -> g_qh (fp16)
//   K2   : h = qh_bk @ xh_b^T /sqrt(E) -> pijk (f32)
//   K3   : softmax rows in place (f32) + fp16 copy -> g_ph
//   K4   : y = ph_bk @ xth_b^T        -> xid (f32)
// ============================================================================

#define NTHREADS 256
#define BK 64
#define TILEB 16384                 // 128 rows x 128 bytes (64 fp16)
#define STAGEB (2*TILEB)            // A + B
#define NSTAGE 3
#define DSMEMB (NSTAGE*STAGEB)      // 98304

__device__ __half g_qh [4096UL*4096UL];      // 32 MB
__device__ __half g_xh [4UL*1024UL*512UL];   //  4 MB
__device__ __half g_wh [4096UL*512UL];       //  4 MB
__device__ __half g_xth[4UL*512UL*1024UL];   //  4 MB
__device__ __half g_ph [32768UL*1024UL];     // 64 MB

// ---------------------------------------------------------------- helpers
__device__ __forceinline__ uint32_t smem_u32(const void* p) {
    uint32_t a;
    asm("{ .reg .u64 t; cvta.to.shared.u64 t, %1; cvt.u32.u64 %0, t; }"
        : "=r"(a) : "l"(p));
    return a;
}
#define CP16(d, s) \
    asm volatile("cp.async.cg.shared.global [%0], [%1], 16;" :: "r"(d), "l"(s))
#define CP_COMMIT() asm volatile("cp.async.commit_group;" ::: "memory")
#define CP_WAIT1()  asm volatile("cp.async.wait_group 1;" ::: "memory")

#define LDSM4(r, a) \
    asm volatile("ldmatrix.sync.aligned.m8n8.x4.shared.b16 {%0,%1,%2,%3}, [%4];" \
        : "=r"((r)[0]), "=r"((r)[1]), "=r"((r)[2]), "=r"((r)[3]) : "r"(a))

__device__ __forceinline__ void mma_f16(float c[4], const uint32_t a[4],
                                        uint32_t b0, uint32_t b1) {
    asm volatile(
        "mma.sync.aligned.m16n8k16.row.col.f32.f16.f16.f32 "
        "{%0,%1,%2,%3}, {%4,%5,%6,%7}, {%8,%9}, {%0,%1,%2,%3};"
        : "+f"(c[0]), "+f"(c[1]), "+f"(c[2]), "+f"(c[3])
        : "r"(a[0]), "r"(a[1]), "r"(a[2]), "r"(a[3]), "r"(b0), "r"(b1));
}

// load 128 rows x 64 fp16 (row stride ld elems) into XOR-swizzled smem tile
__device__ __forceinline__ void load_tile_h(uint32_t dst, const __half* g, int ld, int tid) {
#pragma unroll
    for (int i = 0; i < 4; i++) {
        int idx = tid + i * NTHREADS;     // 0..1023
        int row = idx >> 3;
        int c   = idx & 7;                // 16B chunk
        uint32_t off = (uint32_t)(row << 7) | (uint32_t)(((c ^ (row & 7)) << 4));
        CP16(dst + off, g + (size_t)row * ld + (c << 3));
    }
}

// ============================================================================
// NT GEMM (fp16 in, f32 acc): C[m,n] = alpha * sum_k A[m,k]*B[n,k]
// CTA tile 128x128, BK=64, 8 warps (2x4), warp tile 64x32, 3-stage pipeline.
// ============================================================================
__global__ void __launch_bounds__(NTHREADS, 2)
gemm_h(const __half* __restrict__ A, int lda, long sAb, long sAk,
       const __half* __restrict__ B, int ldb, long sBb, long sBk,
       void* __restrict__ Cv, int ldc, long sCb, long sCk,
       int Kdim, float alpha, int Kcnt, int halfOut)
{
    extern __shared__ __half smh[];
    const uint32_t smb = smem_u32(smh);

    const int tid  = threadIdx.x;
    const int wid  = tid >> 5;
    const int lane = tid & 31;
    const int gid  = lane >> 2;
    const int tg   = lane & 3;
    const int warpMoff = (wid >> 2) * 64;   // 0,64
    const int warpNoff = (wid & 3) * 32;    // 0..96

    const int z  = blockIdx.z;
    const int zb = z / Kcnt;
    const int zk = z - zb * Kcnt;
    const __half* Ab = A + (size_t)zb * sAb + (size_t)zk * sAk + (size_t)(blockIdx.y * 128) * lda;
    const __half* Bb = B + (size_t)zb * sBb + (size_t)zk * sBk + (size_t)(blockIdx.x * 128) * ldb;
    const size_t cOff = (size_t)zb * sCb + (size_t)zk * sCk
                      + (size_t)(blockIdx.y * 128) * ldc + (size_t)(blockIdx.x * 128);

    const int numK = Kdim >> 6;

    float c[4][4][4];
#pragma unroll
    for (int i = 0; i < 4; i++)
#pragma unroll
        for (int j = 0; j < 4; j++)
#pragma unroll
            for (int r = 0; r < 4; r++) c[i][j][r] = 0.0f;

    // fixed per-lane ldmatrix row components
    const int rlA = lane & 15;
    const int hiA = lane >> 4;
    const int rlB = ((lane >> 4) << 3) + (lane & 7);
    const int hiB = (lane >> 3) & 1;

    // ---- prologue: stages 0 and 1
    load_tile_h(smb,          Ab, lda, tid);
    load_tile_h(smb + TILEB,  Bb, ldb, tid);
    CP_COMMIT();
    if (numK > 1) {
        load_tile_h(smb + STAGEB,         Ab + BK, lda, tid);
        load_tile_h(smb + STAGEB + TILEB, Bb + BK, ldb, tid);
    }
    CP_COMMIT();

    int buf = 0;
    for (int kt = 0; kt < numK; kt++) {
        CP_WAIT1();               // stage kt resident (<=1 group pending)
        __syncthreads();          // all warps done reading the buf we refill next

        // prefetch stage kt+2 (covered by 2 compute iterations)
        const int nk = kt + 2;
        if (nk < numK) {
            int nbuf = buf + 2; if (nbuf >= NSTAGE) nbuf -= NSTAGE;
            const uint32_t nbb = smb + nbuf * STAGEB;
            load_tile_h(nbb,         Ab + nk * BK, lda, tid);
            load_tile_h(nbb + TILEB, Bb + nk * BK, ldb, tid);
        }
        CP_COMMIT();              // one group per iteration, always

        const uint32_t At = smb + buf * STAGEB;
        const uint32_t Bt = At + TILEB;

#pragma unroll
        for (int kk = 0; kk < 4; kk++) {
            uint32_t a[4][4], bb[2][4];
            const int cA = kk * 2 + hiA;
            const int cB = kk * 2 + hiB;
#pragma unroll
            for (int i = 0; i < 4; i++) {
                const int row = warpMoff + i * 16 + rlA;
                uint32_t ad = At + ((uint32_t)row << 7)
                            + (uint32_t)(((cA ^ (row & 7)) << 4));
                LDSM4(a[i], ad);
            }
#pragma unroll
            for (int j = 0; j < 2; j++) {
                const int row = warpNoff + j * 16 + rlB;
                uint32_t bd = Bt + ((uint32_t)row << 7)
                            + (uint32_t)(((cB ^ (row & 7)) << 4));
                LDSM4(bb[j], bd);
            }
#pragma unroll
            for (int i = 0; i < 4; i++)
#pragma unroll
                for (int jj = 0; jj < 4; jj++)
                    mma_f16(c[i][jj], a[i], bb[jj >> 1][(jj & 1) * 2],
                                             bb[jj >> 1][(jj & 1) * 2 + 1]);
        }

        if (++buf == NSTAGE) buf = 0;
    }

    // ---- epilogue
    if (halfOut) {
        __half* Cb = (__half*)Cv + cOff;
#pragma unroll
        for (int i = 0; i < 4; i++) {
            const int r0 = warpMoff + i * 16 + gid;
#pragma unroll
            for (int jj = 0; jj < 4; jj++) {
                const int cc = warpNoff + jj * 8 + tg * 2;
                *(__half2*)(Cb + (size_t)r0 * ldc + cc) =
                    __floats2half2_rn(alpha * c[i][jj][0], alpha * c[i][jj][1]);
                *(__half2*)(Cb + (size_t)(r0 + 8) * ldc + cc) =
                    __floats2half2_rn(alpha * c[i][jj][2], alpha * c[i][jj][3]);
            }
        }
    } else {
        float* Cb = (float*)Cv + cOff;
#pragma unroll
        for (int i = 0; i < 4; i++) {
            const int r0 = warpMoff + i * 16 + gid;
#pragma unroll
            for (int jj = 0; jj < 4; jj++) {
                const int cc = warpNoff + jj * 8 + tg * 2;
                float2 v0, v1;
                v0.x = alpha * c[i][jj][0]; v0.y = alpha * c[i][jj][1];
                v1.x = alpha * c[i][jj][2]; v1.y = alpha * c[i][jj][3];
                *(float2*)(Cb + (size_t)r0 * ldc + cc)       = v0;
                *(float2*)(Cb + (size_t)(r0 + 8) * ldc + cc) = v1;
            }
        }
    }
}

// ============================================================================
// prep: f32 -> fp16
// ============================================================================
__global__ void cvt_h(const float* __restrict__ in, __half* __restrict__ out, int n4)
{
    int i = blockIdx.x * blockDim.x + threadIdx.x;
    if (i >= n4) return;
    float4 v = ((const float4*)in)[i];
    ((__half2*)out)[2 * i]     = __floats2half2_rn(v.x, v.y);
    ((__half2*)out)[2 * i + 1] = __floats2half2_rn(v.z, v.w);
}

// transpose xsa (b,1024,512) f32 -> g_xth (b,512,1024) fp16
__global__ void transpose_h(const float* __restrict__ in, __half* __restrict__ out)
{
    __shared__ float t[32][33];
    const int b = blockIdx.z;
    const int l0 = blockIdx.x * 32, e0 = blockIdx.y * 32;
    in  += (size_t)b * 524288;
    out += (size_t)b * 524288;
    const int x = threadIdx.x, y = threadIdx.y;  // 32 x 8
#pragma unroll
    for (int i = 0; i < 32; i += 8)
        t[y + i][x] = in[(size_t)(l0 + y + i) * 512 + e0 + x];
    __syncthreads();
#pragma unroll
    for (int i = 0; i < 32; i += 8)
        out[(size_t)(e0 + y + i) * 1024 + l0 + x] = __float2half_rn(t[x][y + i]);
}

// ============================================================================
// softmax rows of 1024, in place (f32); also writes fp16 copy to ph
// ============================================================================
__global__ void softmax_rows_kernel(float* __restrict__ p, __half* __restrict__ ph)
{
    __shared__ float red[32];
    const size_t roff = (size_t)blockIdx.x * 1024;
    float* row = p + roff;
    const int t = threadIdx.x;

    float4 v = ((const float4*)row)[t];

    float m = fmaxf(fmaxf(v.x, v.y), fmaxf(v.z, v.w));
#pragma unroll
    for (int o = 16; o; o >>= 1) m = fmaxf(m, __shfl_xor_sync(0xffffffffu, m, o));
    if ((t & 31) == 0) red[t >> 5] = m;
    __syncthreads();
    if (t < 32) {
        float mm = (t < 8) ? red[t] : -CUDART_INF_F;
#pragma unroll
        for (int o = 4; o; o >>= 1) mm = fmaxf(mm, __shfl_xor_sync(0xffffffffu, mm, o));
        if (t == 0) red[0] = mm;
    }
    __syncthreads();
    m = red[0];
    __syncthreads();

    v.x = __expf(v.x - m); v.y = __expf(v.y - m);
    v.z = __expf(v.z - m); v.w = __expf(v.w - m);

    float s = v.x + v.y + v.z + v.w;
#pragma unroll
    for (int o = 16; o; o >>= 1) s += __shfl_xor_sync(0xffffffffu, s, o);
    if ((t & 31) == 0) red[t >> 5] = s;
    __syncthreads();
    if (t < 32) {
        float ss = (t < 8) ? red[t] : 0.0f;
#pragma unroll
        for (int o = 4; o; o >>= 1) ss += __shfl_xor_sync(0xffffffffu, ss, o);
        if (t == 0) red[0] = ss;
    }
    __syncthreads();
    const float inv = 1.0f / red[0];

    v.x *= inv; v.y *= inv; v.z *= inv; v.w *= inv;
    ((float4*)row)[t] = v;

    __half2* pp = (__half2*)(ph + roff);
    pp[2 * t]     = __floats2half2_rn(v.x, v.y);
    pp[2 * t + 1] = __floats2half2_rn(v.z, v.w);
}

// ============================================================================
extern "C" void kernel_launch(void* const* d_in, const int* in_sizes, int n_in,
                              void* d_out, int out_size)
{
    (void)in_sizes; (void)n_in; (void)out_size;
    const float* xsa = (const float*)d_in[0];   // (4,1024,512)
    const float* Wq  = (const float*)d_in[1];   // (4096,512)
    float* out  = (float*)d_out;
    float* xid  = out;                          // 16777216 floats
    float* pijk = out + 16777216UL;             // 33554432 floats

    __half *qh, *xh, *wh, *xth, *ph;
    cudaGetSymbolAddress((void**)&qh,  g_qh);
    cudaGetSymbolAddress((void**)&xh,  g_xh);
    cudaGetSymbolAddress((void**)&wh,  g_wh);
    cudaGetSymbolAddress((void**)&xth, g_xth);
    cudaGetSymbolAddress((void**)&ph,  g_ph);

    cudaFuncSetAttribute(gemm_h, cudaFuncAttributeMaxDynamicSharedMemorySize, DSMEMB);

    const float inv_sqrt_e = 0.044194173824159216f;  // 1/sqrt(512)

    // prep
    cvt_h<<<2048, 256>>>(xsa, xh, 524288);
    cvt_h<<<2048, 256>>>(Wq,  wh, 524288);
    transpose_h<<<dim3(32, 16, 4), dim3(32, 8)>>>(xsa, xth);

    // K1: q = xh @ wh^T   M=4096 N=4096 K=512, fp16 out
    gemm_h<<<dim3(32, 32, 1), NTHREADS, DSMEMB>>>(
        xh, 512, 0, 0,
        wh, 512, 0, 0,
        qh, 4096, 0, 0,
        512, 1.0f, 1, 1);

    // K2: logits = qh_bk @ xh_b^T / sqrt(E)   M=1024 N=1024 K=512, 32 batches
    gemm_h<<<dim3(8, 8, 32), NTHREADS, DSMEMB>>>(
        qh, 4096, 4194304L, 512L,
        xh, 512,  524288L,  0L,
        pijk, 8192, 8388608L, 1024L,
        512, inv_sqrt_e, 8, 0);

    // K3: softmax -> pijk f32 (output) + ph fp16 (K4 operand)
    softmax_rows_kernel<<<32768, 256>>>(pijk, ph);

    // K4: y = ph_bk @ xth_b^T   M=1024 N=512 K=1024, 32 batches
    // ph layout (b,l,k,m): row stride 8192, k stride 1024
    gemm_h<<<dim3(4, 8, 32), NTHREADS, DSMEMB>>>(
        ph,  8192, 8388608L, 1024L,
        xth, 1024, 524288L,  0L,
        xid, 4096, 4194304L, 512L,
        1024, 1.0f, 8, 0);
}